// round 16
// baseline (speedup 1.0000x reference)
#include <cuda_runtime.h>
#include <cuda_bf16.h>
#include <stdint.h>
#include <stddef.h>
#include <math.h>

typedef unsigned int u32;

// ---------------- problem dims (fixed) ----------------
#define kN1 80000
#define kN2 16000
#define kN3 4096
#define kE1 256000
#define kE2 65536
// conv1: 256 -> 8 heads x 64 (concat 512). conv2: 512 -> 4 heads x 64, mean.
// GAT aggregation commutes with projection: aggregate raw features first.
// GEMM1 split: D = Ah*Bh + Ah*Bl + Al*Bh, A-hi loaded once in the mainloop.
// Aggregation kernels use zero-padded edge chunks: one fully-unrolled
// high-MLP inner loop, no runtime-trip-count slow path.

// ---------------- scratch (device globals; no allocs) ----------------
__device__ __align__(16) float g_h1 [8192000];   // [16000,512] conv1 out (ELU, fp32)
__device__ __align__(16) float g_es1[kN1*8];
__device__ __align__(16) float g_ed1[kN2*8];
__device__ __align__(16) float g_es2[kN2*4];
__device__ __align__(16) float g_ed2[kN3*4];
__device__ int   g_deg1[kN2], g_cnt1[kN2], g_off1[kN2+1], g_csr1[kE1];
__device__ int   g_deg2[kN3], g_cnt2[kN3], g_off2[kN3+1], g_csr2[kE2];
__device__ __align__(16) float g_v1s[2048], g_v1d[2048];
__device__ __align__(16) float g_v2s[2048], g_v2d[2048];
__device__ __align__(16) float g_w2v[2048];
__device__ __align__(16) float g_u[128];
__device__ float g_c0;

// bf16 split operands. A1 = [Ah|Al] per head, B1 = [Bh|Bl] (512-wide rows).
__device__ __align__(16) __nv_bfloat16 g_x1a[65536000];  // [16000][8][512]
__device__ __align__(16) __nv_bfloat16 g_w1a[512*512];   // [n=512][512]

// ---------------- fused setup + degree count ----------------
__global__ void k_setup(const float* __restrict__ W1s, const float* __restrict__ W1d,
                        const float* __restrict__ a1s, const float* __restrict__ a1d,
                        const float* __restrict__ W2s, const float* __restrict__ W2d,
                        const float* __restrict__ a2s, const float* __restrict__ a2d,
                        const float* __restrict__ fW,  const float* __restrict__ fb,
                        const float* __restrict__ oW,  const float* __restrict__ ob,
                        const float* __restrict__ b2,
                        const int* __restrict__ dst1,  const int* __restrict__ dst2) {
    int i = blockIdx.x * blockDim.x + threadIdx.x;
    if (i < 2048) {
        int h = i >> 8, k = i & 255;
        float s = 0.f;
        for (int c = 0; c < 64; c++) s += W1s[k * 512 + h * 64 + c] * a1s[h * 64 + c];
        g_v1s[i] = s;
    } else if (i < 4096) {
        int j = i - 2048, h = j >> 8, k = j & 255;
        float s = 0.f;
        for (int c = 0; c < 64; c++) s += W1d[k * 512 + h * 64 + c] * a1d[h * 64 + c];
        g_v1d[j] = s;
    } else if (i < 6144) {
        int j = i - 4096, h = j >> 9, k = j & 511;
        float s = 0.f;
        for (int c = 0; c < 64; c++) s += W2s[k * 256 + h * 64 + c] * a2s[h * 64 + c];
        g_v2s[j] = s;
    } else if (i < 8192) {
        int j = i - 6144, h = j >> 9, k = j & 511;
        float s = 0.f;
        for (int c = 0; c < 64; c++) s += W2d[k * 256 + h * 64 + c] * a2d[h * 64 + c];
        g_v2d[j] = s;
    } else if (i < 8320) {
        int j = i - 8192;
        float s = 0.f;
        for (int jj = 0; jj < 64; jj++) s += fW[j * 64 + jj] * oW[64 + jj];
        g_u[j] = s;
    } else if (i == 8320) {
        float s = ob[0];
        for (int j = 0; j < 64; j++) s += fb[j] * oW[64 + j];
        for (int j = 0; j < 64; j++) s += b2[j] * oW[j];
        g_c0 = s;
    } else if (i < 10369) {
        int j = i - 8321, h = j >> 9, kk = j & 511;
        float s = 0.f;
        for (int n = 0; n < 64; n++) s += W2s[kk * 256 + h * 64 + n] * oW[n];
        g_w2v[j] = 0.25f * s;
    } else if (i < 141441) {
        int j = i - 10369;             // W1s elem j = k*512 + n
        int k = j >> 9, n = j & 511;
        float v = W1s[j];
        __nv_bfloat16 h = __float2bfloat16(v);
        __nv_bfloat16 l = __float2bfloat16(v - __bfloat162float(h));
        g_w1a[n * 512 + k]       = h;
        g_w1a[n * 512 + 256 + k] = l;
    } else if (i < 141441 + kE1) {
        atomicAdd(&g_deg1[dst1[i - 141441]], 1);
    } else if (i < 141441 + kE1 + kE2) {
        atomicAdd(&g_deg2[dst2[i - 141441 - kE1]], 1);
    }
}

// ---------------- scan (also resets deg/cnt for the next graph replay) ----------
__global__ void k_scan() {
    int which = blockIdx.x;
    int* deg = (which == 0) ? g_deg1 : g_deg2;
    int* cnt = (which == 0) ? g_cnt1 : g_cnt2;
    int* off = (which == 0) ? g_off1 : g_off2;
    int n    = (which == 0) ? kN2    : kN3;
    __shared__ int wsum[32];
    __shared__ int carry;
    int t = threadIdx.x, lane = t & 31, wid = t >> 5;
    if (t == 0) carry = 0;
    __syncthreads();
    for (int base = 0; base < n; base += 1024) {
        int i = base + t;
        int v = (i < n) ? deg[i] : 0;
        int s = v;
#pragma unroll
        for (int d = 1; d < 32; d <<= 1) {
            int u = __shfl_up_sync(0xffffffffu, s, d);
            if (lane >= d) s += u;
        }
        if (lane == 31) wsum[wid] = s;
        __syncthreads();
        if (wid == 0) {
            int ws = wsum[lane];
#pragma unroll
            for (int d = 1; d < 32; d <<= 1) {
                int u = __shfl_up_sync(0xffffffffu, ws, d);
                if (lane >= d) ws += u;
            }
            wsum[lane] = ws;
        }
        __syncthreads();
        int pre = (wid > 0) ? wsum[wid - 1] : 0;
        int c = carry;
        if (i < n) {
            off[i] = c + pre + s - v;
            deg[i] = 0;
            cnt[i] = 0;
        }
        __syncthreads();
        if (t == 1023) carry = c + wsum[31];
        __syncthreads();
    }
    if (t == 0) off[n] = carry;
}

// ---------------- merged: CSR scatter (blocks < 1256) || scores1 (rest) ----------
__global__ void k_scsc(const int* __restrict__ src1, const int* __restrict__ dst1,
                       const int* __restrict__ src2, const int* __restrict__ dst2,
                       const float* __restrict__ x) {
    if (blockIdx.x < 1256) {
        int i = blockIdx.x * 256 + threadIdx.x;
        if (i < kE1) {
            int d = dst1[i];
            int p = g_off1[d] + atomicAdd(&g_cnt1[d], 1);
            g_csr1[p] = src1[i];
        } else if (i < kE1 + kE2) {
            int j = i - kE1;
            int d = dst2[j];
            int p = g_off2[d] + atomicAdd(&g_cnt2[d], 1);
            g_csr2[p] = src2[j];
        }
        return;
    }
    int gw = ((blockIdx.x - 1256) * 256 + threadIdx.x) >> 5;
    int lane = threadIdx.x & 31;
    if (gw >= kN1) return;
    const float* xr = x + (size_t)gw * 256 + lane * 8;
    float4 x0 = *(const float4*)(xr);
    float4 x1 = *(const float4*)(xr + 4);
    bool dd = (gw < kN2);
    float aS[8];
    float aD[8];
#pragma unroll
    for (int h = 0; h < 8; h++) {
        const float* vp = g_v1s + h * 256 + lane * 8;
        float4 v0 = *(const float4*)(vp);
        float4 v1 = *(const float4*)(vp + 4);
        aS[h] = x0.x*v0.x + x0.y*v0.y + x0.z*v0.z + x0.w*v0.w
              + x1.x*v1.x + x1.y*v1.y + x1.z*v1.z + x1.w*v1.w;
    }
    if (dd) {
#pragma unroll
        for (int h = 0; h < 8; h++) {
            const float* vp = g_v1d + h * 256 + lane * 8;
            float4 v0 = *(const float4*)(vp);
            float4 v1 = *(const float4*)(vp + 4);
            aD[h] = x0.x*v0.x + x0.y*v0.y + x0.z*v0.z + x0.w*v0.w
                  + x1.x*v1.x + x1.y*v1.y + x1.z*v1.z + x1.w*v1.w;
        }
    }
#pragma unroll
    for (int h = 0; h < 8; h++) {
#pragma unroll
        for (int s = 16; s >= 1; s >>= 1) aS[h] += __shfl_down_sync(0xffffffffu, aS[h], s);
    }
    if (dd) {
#pragma unroll
        for (int h = 0; h < 8; h++) {
#pragma unroll
            for (int s = 16; s >= 1; s >>= 1) aD[h] += __shfl_down_sync(0xffffffffu, aD[h], s);
        }
    }
    if (lane == 0) {
#pragma unroll
        for (int h = 0; h < 8; h++) g_es1[gw * 8 + h] = aS[h];
        if (dd) {
#pragma unroll
            for (int h = 0; h < 8; h++) g_ed1[gw * 8 + h] = aD[h];
        }
    }
}

// ---------------- scores2: lane owns 16 contiguous cols of 512 ----------------
__global__ void k_scores2() {
    int gw = (blockIdx.x * blockDim.x + threadIdx.x) >> 5;
    int lane = threadIdx.x & 31;
    if (gw >= kN2) return;
    const float* xr = g_h1 + (size_t)gw * 512 + lane * 16;
    float4 xv[4];
#pragma unroll
    for (int q = 0; q < 4; q++) xv[q] = *(const float4*)(xr + q * 4);
    bool dd = (gw < kN3);
    float aS[4];
    float aD[4];
#pragma unroll
    for (int h = 0; h < 4; h++) {
        const float* vp = g_v2s + h * 512 + lane * 16;
        float s = 0.f;
#pragma unroll
        for (int q = 0; q < 4; q++) {
            float4 v = *(const float4*)(vp + q * 4);
            s += xv[q].x*v.x + xv[q].y*v.y + xv[q].z*v.z + xv[q].w*v.w;
        }
        aS[h] = s;
    }
    if (dd) {
#pragma unroll
        for (int h = 0; h < 4; h++) {
            const float* vp = g_v2d + h * 512 + lane * 16;
            float s = 0.f;
#pragma unroll
            for (int q = 0; q < 4; q++) {
                float4 v = *(const float4*)(vp + q * 4);
                s += xv[q].x*v.x + xv[q].y*v.y + xv[q].z*v.z + xv[q].w*v.w;
            }
            aD[h] = s;
        }
    }
#pragma unroll
    for (int h = 0; h < 4; h++) {
#pragma unroll
        for (int s = 16; s >= 1; s >>= 1) aS[h] += __shfl_down_sync(0xffffffffu, aS[h], s);
    }
    if (dd) {
#pragma unroll
        for (int h = 0; h < 4; h++) {
#pragma unroll
            for (int s = 16; s >= 1; s >>= 1) aD[h] += __shfl_down_sync(0xffffffffu, aD[h], s);
        }
    }
    if (lane == 0) {
#pragma unroll
        for (int h = 0; h < 4; h++) g_es2[gw * 4 + h] = aS[h];
        if (dd) {
#pragma unroll
            for (int h = 0; h < 4; h++) g_ed2[gw * 4 + h] = aD[h];
        }
    }
}

// ---------------- conv1 aggregation: 256 thr (1 col each), zero-padded chunks ----
__global__ void __launch_bounds__(256) k_agg1x(const float* __restrict__ x) {
    int d = blockIdx.x;
    int t = threadIdx.x;
    int hE = t & 7;
    int lE = t >> 3;          // 0..31; lanes 0..15 used per 16-edge chunk

    __shared__ float sh_red[256];
    __shared__ float sh_den[8];
    __shared__ float sh_selfw[8];
    __shared__ float sh_ed[8];
    __shared__ __align__(16) float sh_w[16 * 8];   // [j][h]
    __shared__ int   sh_src[16];

    if (t < 8) sh_ed[t] = g_ed1[d * 8 + t];
    __syncthreads();
    float edv = sh_ed[hE];

    int e0 = g_off1[d], e1 = g_off1[d + 1];

    float acc[8];
#pragma unroll
    for (int h = 0; h < 8; h++) acc[h] = 0.f;
    float den = 0.f;

    for (int base = e0; base < e1; base += 16) {
        int cnt = e1 - base;          // clamp via predication below
        if (lE < 16) {                // threads t<128 own (edge lE, head hE)
            if (lE < cnt) {
                int s = g_csr1[base + lE];
                if (hE == 0) sh_src[lE] = s;
                float a = g_es1[s * 8 + hE] + edv;
                a = a > 0.f ? a : 0.2f * a;
                float ex = __expf(a);
                sh_w[lE * 8 + hE] = ex;
                den += ex;
            } else {
                if (hE == 0) sh_src[lE] = d;   // valid row; weight 0
                sh_w[lE * 8 + hE] = 0.f;
            }
        }
        __syncthreads();
        float v[16];
#pragma unroll
        for (int j = 0; j < 16; j++)
            v[j] = x[(size_t)sh_src[j] * 256 + t];
#pragma unroll
        for (int j = 0; j < 16; j++) {
            float4 wa = *(const float4*)(sh_w + j * 8);
            float4 wb = *(const float4*)(sh_w + j * 8 + 4);
            acc[0] += wa.x * v[j];
            acc[1] += wa.y * v[j];
            acc[2] += wa.z * v[j];
            acc[3] += wa.w * v[j];
            acc[4] += wb.x * v[j];
            acc[5] += wb.y * v[j];
            acc[6] += wb.z * v[j];
            acc[7] += wb.w * v[j];
        }
        __syncthreads();
    }

    sh_red[t] = den;                  // valid in t<128 (lE<16); others are 0
    __syncthreads();
#pragma unroll
    for (int half = 8; half >= 1; half >>= 1) {
        if (lE < half) sh_red[t] += sh_red[t + half * 8];
        __syncthreads();
    }
    if (t < 8) {
        float a = g_es1[d * 8 + t] + sh_ed[t];
        a = a > 0.f ? a : 0.2f * a;
        float ex = __expf(a);
        sh_selfw[t] = ex;
        sh_den[t] = sh_red[t] + ex;
    }
    __syncthreads();

    float xv = x[(size_t)d * 256 + t];
#pragma unroll
    for (int h = 0; h < 8; h++) {
        float ws  = sh_selfw[h];
        float inv = 1.f / sh_den[h];
        float a  = (acc[h] + ws * xv) * inv;
        __nv_bfloat16 hb = __float2bfloat16(a);
        __nv_bfloat16 lb = __float2bfloat16(a - __bfloat162float(hb));
        size_t bo = ((size_t)d * 8 + h) * 512 + t;
        g_x1a[bo]       = hb;
        g_x1a[bo + 256] = lb;
    }
}

// ---------------- conv2 aggregation (zero-padded) + w2v dot + output tail --------
__global__ void __launch_bounds__(128) k_agg2x(const float* __restrict__ flat,
                                               const float* __restrict__ last,
                                               const float* __restrict__ oW,
                                               float* __restrict__ out) {
    int d = blockIdx.x;
    int t = threadIdx.x;
    int hE = t & 3;
    int lE = t >> 2;          // 0..31
    int c  = t * 4;

    __shared__ float sh_red[128];
    __shared__ float sh_den[4];
    __shared__ float sh_selfw[4];
    __shared__ float sh_ed[4];
    __shared__ __align__(16) float sh_w[32 * 4];   // [j][h]
    __shared__ int   sh_src[32];

    if (t < 4) sh_ed[t] = g_ed2[d * 4 + t];
    __syncthreads();
    float edv = sh_ed[hE];

    int e0 = g_off2[d], e1 = g_off2[d + 1];

    float acc[4][4];
#pragma unroll
    for (int h = 0; h < 4; h++) {
#pragma unroll
        for (int q = 0; q < 4; q++) acc[h][q] = 0.f;
    }
    float den = 0.f;

    for (int base = e0; base < e1; base += 32) {
        int cnt = e1 - base;
        if (lE < cnt) {
            int s = g_csr2[base + lE];
            if (hE == 0) sh_src[lE] = s;
            float a = g_es2[s * 4 + hE] + edv;
            a = a > 0.f ? a : 0.2f * a;
            float ex = __expf(a);
            sh_w[lE * 4 + hE] = ex;
            den += ex;
        } else {
            if (hE == 0) sh_src[lE] = d;
            sh_w[lE * 4 + hE] = 0.f;
        }
        __syncthreads();
#pragma unroll 8
        for (int j = 0; j < 32; j++) {
            float4 v = *(const float4*)(g_h1 + (size_t)sh_src[j] * 512 + c);
            float4 w = *(const float4*)(sh_w + j * 4);
            acc[0][0] += w.x * v.x; acc[0][1] += w.x * v.y;
            acc[0][2] += w.x * v.z; acc[0][3] += w.x * v.w;
            acc[1][0] += w.y * v.x; acc[1][1] += w.y * v.y;
            acc[1][2] += w.y * v.z; acc[1][3] += w.y * v.w;
            acc[2][0] += w.z * v.x; acc[2][1] += w.z * v.y;
            acc[2][2] += w.z * v.z; acc[2][3] += w.z * v.w;
            acc[3][0] += w.w * v.x; acc[3][1] += w.w * v.y;
            acc[3][2] += w.w * v.z; acc[3][3] += w.w * v.w;
        }
        __syncthreads();
    }

    sh_red[t] = den;
    __syncthreads();
#pragma unroll
    for (int half = 16; half >= 1; half >>= 1) {
        if (lE < half) sh_red[t] += sh_red[t + half * 4];
        __syncthreads();
    }
    if (t < 4) {
        float a = g_es2[d * 4 + t] + sh_ed[t];
        a = a > 0.f ? a : 0.2f * a;
        float ex = __expf(a);
        sh_selfw[t] = ex;
        sh_den[t] = sh_red[t] + ex;
    }
    __syncthreads();

    float4 sv = *(const float4*)(g_h1 + (size_t)d * 512 + c);
    float svv[4];
    svv[0] = sv.x; svv[1] = sv.y; svv[2] = sv.z; svv[3] = sv.w;

    float contrib = 0.f;
#pragma unroll
    for (int h = 0; h < 4; h++) {
        float ws  = sh_selfw[h];
        float inv = 1.f / sh_den[h];
#pragma unroll
        for (int q = 0; q < 4; q++) {
            float a = (acc[h][q] + ws * svv[q]) * inv;
            contrib += a * g_w2v[h * 512 + c + q];
        }
    }
    contrib += flat[(size_t)d * 128 + t] * g_u[t];
    if (t < 64) contrib += last[(size_t)d * 64 + t] * oW[128 + t];

    sh_red[t] = contrib;
    __syncthreads();
#pragma unroll
    for (int half = 64; half >= 1; half >>= 1) {
        if (t < half) sh_red[t] += sh_red[t + half];
        __syncthreads();
    }
    if (t == 0) out[d] = sh_red[0] + g_c0;
}

// ---------------- tensor-core GEMM primitives ----------------
__device__ __forceinline__ void cp16(u32 sm, const void* gp) {
    asm volatile("cp.async.cg.shared.global [%0], [%1], 16;" : : "r"(sm), "l"(gp));
}
__device__ __forceinline__ void cp_commit() {
    asm volatile("cp.async.commit_group;" : :);
}
__device__ __forceinline__ void cp_wait1() {
    asm volatile("cp.async.wait_group 1;" : :);
}
__device__ __forceinline__ void cp_wait0() {
    asm volatile("cp.async.wait_group 0;" : :);
}
__device__ __forceinline__ void ldsm4(u32* r, u32 a) {
    asm volatile("ldmatrix.sync.aligned.m8n8.x4.shared.b16 {%0,%1,%2,%3}, [%4];"
                 : "=r"(r[0]), "=r"(r[1]), "=r"(r[2]), "=r"(r[3]) : "r"(a));
}
__device__ __forceinline__ void ldsm2(u32* r, u32 a) {
    asm volatile("ldmatrix.sync.aligned.m8n8.x2.shared.b16 {%0,%1}, [%2];"
                 : "=r"(r[0]), "=r"(r[1]) : "r"(a));
}
__device__ __forceinline__ void mma16816(float* d, const u32* a, const u32* b) {
    asm volatile("mma.sync.aligned.m16n8k16.row.col.f32.bf16.bf16.f32 "
                 "{%0,%1,%2,%3}, {%4,%5,%6,%7}, {%8,%9}, {%0,%1,%2,%3};"
                 : "+f"(d[0]), "+f"(d[1]), "+f"(d[2]), "+f"(d[3])
                 : "r"(a[0]), "r"(a[1]), "r"(a[2]), "r"(a[3]), "r"(b[0]), "r"(b[1]));
}

// stage loader: A tile 128x32 (row stride 4096), two B tiles 64x32 (row stride 512)
__device__ __forceinline__ void gload(const __nv_bfloat16* A, const __nv_bfloat16* B,
                                      u32 sA, u32 sB0, u32 sB1, int tid, int bm,
                                      int ak0, int b0k, int b1k) {
#pragma unroll
    for (int i = 0; i < 2; i++) {
        int cc = tid + i * 256;
        int row = cc >> 2;
        int kc = (cc & 3) << 3;
        cp16(sA + row * 80 + kc * 2, (const void*)(A + (size_t)(bm + row) * 4096 + ak0 + kc));
    }
    {
        int row = tid >> 2;
        int kc = (tid & 3) << 3;
        cp16(sB0 + row * 80 + kc * 2, (const void*)(B + (size_t)row * 512 + b0k + kc));
        cp16(sB1 + row * 80 + kc * 2, (const void*)(B + (size_t)row * 512 + b1k + kc));
    }
}

// conv1 GEMM: per-head, D = Ah*Bh + Ah*Bl + Al*Bh with A-hi loaded ONCE.
// 16 macro iters: it 0..7 (A-hi x {Bh,Bl}), it 8..15 (A-lo x Bh).
// 128x64 CTA tile, 8 warps (4m x 2n), double-buffered. grid (125, 8).
__global__ void __launch_bounds__(256) k_mma(const float* __restrict__ bias) {
    int head = blockIdx.y;
    const __nv_bfloat16* A = g_x1a + (size_t)head * 512;
    const __nv_bfloat16* B = g_w1a + (size_t)head * 64 * 512;

    __shared__ __nv_bfloat16 smem[20480];   // 40960 B = 2 stages x (10240+5120+5120)
    const int tid  = threadIdx.x;
    const int lane = tid & 31;
    const int w    = tid >> 5;
    const int wm   = (w >> 1) * 32;
    const int wn   = (w & 1) * 32;
    const int bm   = blockIdx.x * 128;
    const u32 sbase = (u32)__cvta_generic_to_shared(smem);

    float acc[2][4][4];
#pragma unroll
    for (int i = 0; i < 2; i++) {
#pragma unroll
        for (int j = 0; j < 4; j++) {
#pragma unroll
            for (int q = 0; q < 4; q++) acc[i][j][q] = 0.f;
        }
    }

    gload(A, B, sbase, sbase + 10240, sbase + 15360, tid, bm, 0, 0, 256);
    cp_commit();

    for (int it = 0; it < 16; it++) {
        if (it + 1 < 16) {
            int ni = it + 1;
            int ak0 = (ni < 8) ? ni * 32 : 256 + (ni - 8) * 32;
            int b0k = (ni < 8) ? ni * 32 : (ni - 8) * 32;
            int b1k = (ni < 8) ? 256 + ni * 32 : (ni - 8) * 32;
            u32 s = (ni & 1) ? (sbase + 20480) : sbase;
            gload(A, B, s, s + 10240, s + 15360, tid, bm, ak0, b0k, b1k);
            cp_commit();
            cp_wait1();
        } else {
            cp_wait0();
        }
        __syncthreads();
        u32 sA  = (it & 1) ? (sbase + 20480) : sbase;
        u32 sB0 = sA + 10240;
        u32 sB1 = sA + 15360;
#pragma unroll
        for (int kk = 0; kk < 2; kk++) {
            u32 a[2][4];
            u32 b[4][2];
#pragma unroll
            for (int i = 0; i < 2; i++) {
                int row = wm + i * 16 + (lane & 15);
                int ko  = kk * 16 + (lane >> 4) * 8;
                ldsm4(a[i], sA + row * 80 + ko * 2);
            }
#pragma unroll
            for (int j = 0; j < 4; j++) {
                int row = wn + j * 8 + (lane & 7);
                int ko  = kk * 16 + ((lane >> 3) & 1) * 8;
                ldsm2(b[j], sB0 + row * 80 + ko * 2);
            }
#pragma unroll
            for (int i = 0; i < 2; i++) {
#pragma unroll
                for (int j = 0; j < 4; j++) mma16816(acc[i][j], a[i], b[j]);
            }
            if (it < 8) {
#pragma unroll
                for (int j = 0; j < 4; j++) {
                    int row = wn + j * 8 + (lane & 7);
                    int ko  = kk * 16 + ((lane >> 3) & 1) * 8;
                    ldsm2(b[j], sB1 + row * 80 + ko * 2);
                }
#pragma unroll
                for (int i = 0; i < 2; i++) {
#pragma unroll
                    for (int j = 0; j < 4; j++) mma16816(acc[i][j], a[i], b[j]);
                }
            }
        }
        __syncthreads();
    }

#pragma unroll
    for (int i = 0; i < 2; i++) {
        int row = bm + wm + i * 16 + (lane >> 2);
#pragma unroll
        for (int j = 0; j < 4; j++) {
            int col = wn + j * 8 + (lane & 3) * 2;
            int gc = head * 64 + col;
            float b0 = bias[gc], b1v = bias[gc + 1];
            float o0 = acc[i][j][0] + b0;
            float o1 = acc[i][j][1] + b1v;
            float o2 = acc[i][j][2] + b0;
            float o3 = acc[i][j][3] + b1v;
            o0 = o0 > 0.f ? o0 : expm1f(o0);
            o1 = o1 > 0.f ? o1 : expm1f(o1);
            o2 = o2 > 0.f ? o2 : expm1f(o2);
            o3 = o3 > 0.f ? o3 : expm1f(o3);
            float2 v0; v0.x = o0; v0.y = o1;
            float2 v1; v1.x = o2; v1.y = o3;
            *(float2*)(g_h1 + (size_t)row * 512 + gc)       = v0;
            *(float2*)(g_h1 + (size_t)(row + 8) * 512 + gc) = v1;
        }
    }
}

// ---------------- launch ----------------
extern "C" void kernel_launch(void* const* d_in, const int* in_sizes, int n_in,
                              void* d_out, int out_size) {
    const float* x    = (const float*)d_in[0];
    const float* flat = (const float*)d_in[1];
    const float* last = (const float*)d_in[2];
    const int* esrc1  = (const int*)d_in[3];
    const int* edst1  = (const int*)d_in[4];
    const int* esrc2  = (const int*)d_in[5];
    const int* edst2  = (const int*)d_in[6];
    const float* W1s  = (const float*)d_in[7];
    const float* W1d  = (const float*)d_in[8];
    const float* a1s  = (const float*)d_in[9];
    const float* a1d  = (const float*)d_in[10];
    const float* b1   = (const float*)d_in[11];
    const float* W2s  = (const float*)d_in[12];
    const float* W2d  = (const float*)d_in[13];
    const float* a2s  = (const float*)d_in[14];
    const float* a2d  = (const float*)d_in[15];
    const float* b2   = (const float*)d_in[16];
    const float* fW   = (const float*)d_in[17];
    const float* fb   = (const float*)d_in[18];
    const float* oW   = (const float*)d_in[19];
    const float* ob   = (const float*)d_in[20];
    float* out        = (float*)d_out;

    (void)in_sizes;
    (void)n_in;
    (void)out_size;

    k_setup<<<1809, 256>>>(W1s, W1d, a1s, a1d, W2s, W2d, a2s, a2d,
                           fW, fb, oW, ob, b2, edst1, edst2);
    k_scan<<<2, 1024>>>();
    k_scsc<<<1256 + 10000, 256>>>(esrc1, edst1, esrc2, edst2, x);

    k_agg1x<<<kN2, 256>>>(x);
    k_mma<<<dim3(125, 8), 256>>>(b1);

    k_scores2<<<(kN2 * 32) / 256, 256>>>();
    k_agg2x<<<kN3, 128>>>(flat, last, oW, out);
}

// round 17
// speedup vs baseline: 1.1735x; 1.1735x over previous
#include <cuda_runtime.h>
#include <cuda_bf16.h>
#include <stdint.h>
#include <stddef.h>
#include <math.h>

typedef unsigned int u32;

// ---------------- problem dims (fixed) ----------------
#define kN1 80000
#define kN2 16000
#define kN3 4096
#define kE1 256000
#define kE2 65536
// conv1: 256 -> 8 heads x 64 (concat 512). conv2: 512 -> 4 heads x 64, mean.
// GAT aggregation commutes with projection: aggregate raw features first.
// GEMM1 split: D = Ah*Bh + Ah*Bl + Al*Bh, A-hi loaded once in the mainloop.

// ---------------- scratch (device globals; no allocs) ----------------
__device__ __align__(16) float g_h1 [8192000];   // [16000,512] conv1 out (ELU, fp32)
__device__ __align__(16) float g_es1[kN1*8];
__device__ __align__(16) float g_ed1[kN2*8];
__device__ __align__(16) float g_es2[kN2*4];
__device__ __align__(16) float g_ed2[kN3*4];
__device__ int   g_deg1[kN2], g_cnt1[kN2], g_off1[kN2+1], g_csr1[kE1];
__device__ int   g_deg2[kN3], g_cnt2[kN3], g_off2[kN3+1], g_csr2[kE2];
__device__ __align__(16) float g_v1s[2048], g_v1d[2048];
__device__ __align__(16) float g_v2s[2048], g_v2d[2048];
__device__ __align__(16) float g_w2v[2048];
__device__ __align__(16) float g_u[128];
__device__ float g_c0;

// bf16 split operands. A1 = [Ah|Al] per head, B1 = [Bh|Bl] (512-wide rows).
__device__ __align__(16) __nv_bfloat16 g_x1a[65536000];  // [16000][8][512]
__device__ __align__(16) __nv_bfloat16 g_w1a[512*512];   // [n=512][512]

// ---------------- fused setup + degree count ----------------
__global__ void k_setup(const float* __restrict__ W1s, const float* __restrict__ W1d,
                        const float* __restrict__ a1s, const float* __restrict__ a1d,
                        const float* __restrict__ W2s, const float* __restrict__ W2d,
                        const float* __restrict__ a2s, const float* __restrict__ a2d,
                        const float* __restrict__ fW,  const float* __restrict__ fb,
                        const float* __restrict__ oW,  const float* __restrict__ ob,
                        const float* __restrict__ b2,
                        const int* __restrict__ dst1,  const int* __restrict__ dst2) {
    int i = blockIdx.x * blockDim.x + threadIdx.x;
    if (i < 2048) {
        int h = i >> 8, k = i & 255;
        float s = 0.f;
        for (int c = 0; c < 64; c++) s += W1s[k * 512 + h * 64 + c] * a1s[h * 64 + c];
        g_v1s[i] = s;
    } else if (i < 4096) {
        int j = i - 2048, h = j >> 8, k = j & 255;
        float s = 0.f;
        for (int c = 0; c < 64; c++) s += W1d[k * 512 + h * 64 + c] * a1d[h * 64 + c];
        g_v1d[j] = s;
    } else if (i < 6144) {
        int j = i - 4096, h = j >> 9, k = j & 511;
        float s = 0.f;
        for (int c = 0; c < 64; c++) s += W2s[k * 256 + h * 64 + c] * a2s[h * 64 + c];
        g_v2s[j] = s;
    } else if (i < 8192) {
        int j = i - 6144, h = j >> 9, k = j & 511;
        float s = 0.f;
        for (int c = 0; c < 64; c++) s += W2d[k * 256 + h * 64 + c] * a2d[h * 64 + c];
        g_v2d[j] = s;
    } else if (i < 8320) {
        int j = i - 8192;
        float s = 0.f;
        for (int jj = 0; jj < 64; jj++) s += fW[j * 64 + jj] * oW[64 + jj];
        g_u[j] = s;
    } else if (i == 8320) {
        float s = ob[0];
        for (int j = 0; j < 64; j++) s += fb[j] * oW[64 + j];
        for (int j = 0; j < 64; j++) s += b2[j] * oW[j];
        g_c0 = s;
    } else if (i < 10369) {
        int j = i - 8321, h = j >> 9, kk = j & 511;
        float s = 0.f;
        for (int n = 0; n < 64; n++) s += W2s[kk * 256 + h * 64 + n] * oW[n];
        g_w2v[j] = 0.25f * s;
    } else if (i < 141441) {
        int j = i - 10369;             // W1s elem j = k*512 + n
        int k = j >> 9, n = j & 511;
        float v = W1s[j];
        __nv_bfloat16 h = __float2bfloat16(v);
        __nv_bfloat16 l = __float2bfloat16(v - __bfloat162float(h));
        g_w1a[n * 512 + k]       = h;
        g_w1a[n * 512 + 256 + k] = l;
    } else if (i < 141441 + kE1) {
        atomicAdd(&g_deg1[dst1[i - 141441]], 1);
    } else if (i < 141441 + kE1 + kE2) {
        atomicAdd(&g_deg2[dst2[i - 141441 - kE1]], 1);
    }
}

// ---------------- scan (also resets deg/cnt for the next graph replay) ----------
__global__ void k_scan() {
    int which = blockIdx.x;
    int* deg = (which == 0) ? g_deg1 : g_deg2;
    int* cnt = (which == 0) ? g_cnt1 : g_cnt2;
    int* off = (which == 0) ? g_off1 : g_off2;
    int n    = (which == 0) ? kN2    : kN3;
    __shared__ int wsum[32];
    __shared__ int carry;
    int t = threadIdx.x, lane = t & 31, wid = t >> 5;
    if (t == 0) carry = 0;
    __syncthreads();
    for (int base = 0; base < n; base += 1024) {
        int i = base + t;
        int v = (i < n) ? deg[i] : 0;
        int s = v;
#pragma unroll
        for (int d = 1; d < 32; d <<= 1) {
            int u = __shfl_up_sync(0xffffffffu, s, d);
            if (lane >= d) s += u;
        }
        if (lane == 31) wsum[wid] = s;
        __syncthreads();
        if (wid == 0) {
            int ws = wsum[lane];
#pragma unroll
            for (int d = 1; d < 32; d <<= 1) {
                int u = __shfl_up_sync(0xffffffffu, ws, d);
                if (lane >= d) ws += u;
            }
            wsum[lane] = ws;
        }
        __syncthreads();
        int pre = (wid > 0) ? wsum[wid - 1] : 0;
        int c = carry;
        if (i < n) {
            off[i] = c + pre + s - v;
            deg[i] = 0;
            cnt[i] = 0;
        }
        __syncthreads();
        if (t == 1023) carry = c + wsum[31];
        __syncthreads();
    }
    if (t == 0) off[n] = carry;
}

// ---------------- merged: CSR scatter (blocks < 1256) || scores1 (rest) ----------
__global__ void k_scsc(const int* __restrict__ src1, const int* __restrict__ dst1,
                       const int* __restrict__ src2, const int* __restrict__ dst2,
                       const float* __restrict__ x) {
    if (blockIdx.x < 1256) {
        int i = blockIdx.x * 256 + threadIdx.x;
        if (i < kE1) {
            int d = dst1[i];
            int p = g_off1[d] + atomicAdd(&g_cnt1[d], 1);
            g_csr1[p] = src1[i];
        } else if (i < kE1 + kE2) {
            int j = i - kE1;
            int d = dst2[j];
            int p = g_off2[d] + atomicAdd(&g_cnt2[d], 1);
            g_csr2[p] = src2[j];
        }
        return;
    }
    int gw = ((blockIdx.x - 1256) * 256 + threadIdx.x) >> 5;
    int lane = threadIdx.x & 31;
    if (gw >= kN1) return;
    const float* xr = x + (size_t)gw * 256 + lane * 8;
    float4 x0 = *(const float4*)(xr);
    float4 x1 = *(const float4*)(xr + 4);
    bool dd = (gw < kN2);
    float aS[8];
    float aD[8];
#pragma unroll
    for (int h = 0; h < 8; h++) {
        const float* vp = g_v1s + h * 256 + lane * 8;
        float4 v0 = *(const float4*)(vp);
        float4 v1 = *(const float4*)(vp + 4);
        aS[h] = x0.x*v0.x + x0.y*v0.y + x0.z*v0.z + x0.w*v0.w
              + x1.x*v1.x + x1.y*v1.y + x1.z*v1.z + x1.w*v1.w;
    }
    if (dd) {
#pragma unroll
        for (int h = 0; h < 8; h++) {
            const float* vp = g_v1d + h * 256 + lane * 8;
            float4 v0 = *(const float4*)(vp);
            float4 v1 = *(const float4*)(vp + 4);
            aD[h] = x0.x*v0.x + x0.y*v0.y + x0.z*v0.z + x0.w*v0.w
                  + x1.x*v1.x + x1.y*v1.y + x1.z*v1.z + x1.w*v1.w;
        }
    }
#pragma unroll
    for (int h = 0; h < 8; h++) {
#pragma unroll
        for (int s = 16; s >= 1; s >>= 1) aS[h] += __shfl_down_sync(0xffffffffu, aS[h], s);
    }
    if (dd) {
#pragma unroll
        for (int h = 0; h < 8; h++) {
#pragma unroll
            for (int s = 16; s >= 1; s >>= 1) aD[h] += __shfl_down_sync(0xffffffffu, aD[h], s);
        }
    }
    if (lane == 0) {
#pragma unroll
        for (int h = 0; h < 8; h++) g_es1[gw * 8 + h] = aS[h];
        if (dd) {
#pragma unroll
            for (int h = 0; h < 8; h++) g_ed1[gw * 8 + h] = aD[h];
        }
    }
}

// ---------------- scores2: lane owns 16 contiguous cols of 512 ----------------
__global__ void k_scores2() {
    int gw = (blockIdx.x * blockDim.x + threadIdx.x) >> 5;
    int lane = threadIdx.x & 31;
    if (gw >= kN2) return;
    const float* xr = g_h1 + (size_t)gw * 512 + lane * 16;
    float4 xv[4];
#pragma unroll
    for (int q = 0; q < 4; q++) xv[q] = *(const float4*)(xr + q * 4);
    bool dd = (gw < kN3);
    float aS[4];
    float aD[4];
#pragma unroll
    for (int h = 0; h < 4; h++) {
        const float* vp = g_v2s + h * 512 + lane * 16;
        float s = 0.f;
#pragma unroll
        for (int q = 0; q < 4; q++) {
            float4 v = *(const float4*)(vp + q * 4);
            s += xv[q].x*v.x + xv[q].y*v.y + xv[q].z*v.z + xv[q].w*v.w;
        }
        aS[h] = s;
    }
    if (dd) {
#pragma unroll
        for (int h = 0; h < 4; h++) {
            const float* vp = g_v2d + h * 512 + lane * 16;
            float s = 0.f;
#pragma unroll
            for (int q = 0; q < 4; q++) {
                float4 v = *(const float4*)(vp + q * 4);
                s += xv[q].x*v.x + xv[q].y*v.y + xv[q].z*v.z + xv[q].w*v.w;
            }
            aD[h] = s;
        }
    }
#pragma unroll
    for (int h = 0; h < 4; h++) {
#pragma unroll
        for (int s = 16; s >= 1; s >>= 1) aS[h] += __shfl_down_sync(0xffffffffu, aS[h], s);
    }
    if (dd) {
#pragma unroll
        for (int h = 0; h < 4; h++) {
#pragma unroll
            for (int s = 16; s >= 1; s >>= 1) aD[h] += __shfl_down_sync(0xffffffffu, aD[h], s);
        }
    }
    if (lane == 0) {
#pragma unroll
        for (int h = 0; h < 4; h++) g_es2[gw * 4 + h] = aS[h];
        if (dd) {
#pragma unroll
            for (int h = 0; h < 4; h++) g_ed2[gw * 4 + h] = aD[h];
        }
    }
}

// ---------------- conv1 aggregation (single-pass softmax) -> split bf16 ----------
// 128 threads, float2 per thread (R14 layout). Fast path prefetches in two
// 8-row batches to cut live registers while keeping MLP=8.
__global__ void __launch_bounds__(128) k_agg1x(const float* __restrict__ x) {
    int d = blockIdx.x;
    int t = threadIdx.x;
    int hE = t & 7;
    int lE = t >> 3;
    int c  = t * 2;

    __shared__ float sh_red[128];
    __shared__ float sh_den[8];
    __shared__ float sh_selfw[8];
    __shared__ float sh_ed[8];
    __shared__ __align__(16) float sh_w[16 * 8];   // [j][h]
    __shared__ int   sh_src[16];

    if (t < 8) sh_ed[t] = g_ed1[d * 8 + t];
    __syncthreads();
    float edv = sh_ed[hE];

    int e0 = g_off1[d], e1 = g_off1[d + 1];

    float acc[8][2];
#pragma unroll
    for (int h = 0; h < 8; h++) { acc[h][0] = 0.f; acc[h][1] = 0.f; }
    float den = 0.f;

    for (int base = e0; base < e1; base += 16) {
        int cnt = min(16, e1 - base);
        if (lE < cnt) {
            int s = g_csr1[base + lE];
            if (hE == 0) sh_src[lE] = s;
            float a = g_es1[s * 8 + hE] + edv;
            a = a > 0.f ? a : 0.2f * a;
            float ex = __expf(a);
            sh_w[lE * 8 + hE] = ex;
            den += ex;
        }
        __syncthreads();
        if (cnt == 16) {
#pragma unroll
            for (int bb = 0; bb < 2; bb++) {
                float2 v[8];
#pragma unroll
                for (int j = 0; j < 8; j++)
                    v[j] = *(const float2*)(x + (size_t)sh_src[bb * 8 + j] * 256 + c);
#pragma unroll
                for (int j = 0; j < 8; j++) {
                    int jj = bb * 8 + j;
                    float4 wa = *(const float4*)(sh_w + jj * 8);
                    float4 wb = *(const float4*)(sh_w + jj * 8 + 4);
                    acc[0][0] += wa.x * v[j].x; acc[0][1] += wa.x * v[j].y;
                    acc[1][0] += wa.y * v[j].x; acc[1][1] += wa.y * v[j].y;
                    acc[2][0] += wa.z * v[j].x; acc[2][1] += wa.z * v[j].y;
                    acc[3][0] += wa.w * v[j].x; acc[3][1] += wa.w * v[j].y;
                    acc[4][0] += wb.x * v[j].x; acc[4][1] += wb.x * v[j].y;
                    acc[5][0] += wb.y * v[j].x; acc[5][1] += wb.y * v[j].y;
                    acc[6][0] += wb.z * v[j].x; acc[6][1] += wb.z * v[j].y;
                    acc[7][0] += wb.w * v[j].x; acc[7][1] += wb.w * v[j].y;
                }
            }
        } else {
            for (int j = 0; j < cnt; j++) {
                float2 v = *(const float2*)(x + (size_t)sh_src[j] * 256 + c);
                float4 wa = *(const float4*)(sh_w + j * 8);
                float4 wb = *(const float4*)(sh_w + j * 8 + 4);
                acc[0][0] += wa.x * v.x; acc[0][1] += wa.x * v.y;
                acc[1][0] += wa.y * v.x; acc[1][1] += wa.y * v.y;
                acc[2][0] += wa.z * v.x; acc[2][1] += wa.z * v.y;
                acc[3][0] += wa.w * v.x; acc[3][1] += wa.w * v.y;
                acc[4][0] += wb.x * v.x; acc[4][1] += wb.x * v.y;
                acc[5][0] += wb.y * v.x; acc[5][1] += wb.y * v.y;
                acc[6][0] += wb.z * v.x; acc[6][1] += wb.z * v.y;
                acc[7][0] += wb.w * v.x; acc[7][1] += wb.w * v.y;
            }
        }
        __syncthreads();
    }

    sh_red[t] = den;
    __syncthreads();
#pragma unroll
    for (int half = 8; half >= 1; half >>= 1) {
        if (lE < half) sh_red[t] += sh_red[t + half * 8];
        __syncthreads();
    }
    if (t < 8) {
        float a = g_es1[d * 8 + t] + sh_ed[t];
        a = a > 0.f ? a : 0.2f * a;
        float ex = __expf(a);
        sh_selfw[t] = ex;
        sh_den[t] = sh_red[t] + ex;
    }
    __syncthreads();

    float2 xv = *(const float2*)(x + (size_t)d * 256 + c);
#pragma unroll
    for (int h = 0; h < 8; h++) {
        float ws  = sh_selfw[h];
        float inv = 1.f / sh_den[h];
        float a0 = (acc[h][0] + ws * xv.x) * inv;
        float a1 = (acc[h][1] + ws * xv.y) * inv;
        __nv_bfloat16 h0 = __float2bfloat16(a0);
        __nv_bfloat16 h1 = __float2bfloat16(a1);
        __nv_bfloat16 l0 = __float2bfloat16(a0 - __bfloat162float(h0));
        __nv_bfloat16 l1 = __float2bfloat16(a1 - __bfloat162float(h1));
        __nv_bfloat162 hi2; hi2.x = h0; hi2.y = h1;
        __nv_bfloat162 lo2; lo2.x = l0; lo2.y = l1;
        size_t bo = ((size_t)d * 8 + h) * 512 + c;
        *(__nv_bfloat162*)(g_x1a + bo)       = hi2;
        *(__nv_bfloat162*)(g_x1a + bo + 256) = lo2;
    }
}

// ---------------- conv2 aggregation (single-pass) + w2v dot + output tail --------
__global__ void __launch_bounds__(128) k_agg2x(const float* __restrict__ flat,
                                               const float* __restrict__ last,
                                               const float* __restrict__ oW,
                                               float* __restrict__ out) {
    int d = blockIdx.x;
    int t = threadIdx.x;
    int hE = t & 3;
    int lE = t >> 2;
    int c  = t * 4;

    __shared__ float sh_red[128];
    __shared__ float sh_den[4];
    __shared__ float sh_selfw[4];
    __shared__ float sh_ed[4];
    __shared__ __align__(16) float sh_w[32 * 4];   // [j][h]
    __shared__ int   sh_src[32];

    if (t < 4) sh_ed[t] = g_ed2[d * 4 + t];
    __syncthreads();
    float edv = sh_ed[hE];

    int e0 = g_off2[d], e1 = g_off2[d + 1];

    float acc[4][4];
#pragma unroll
    for (int h = 0; h < 4; h++) {
#pragma unroll
        for (int q = 0; q < 4; q++) acc[h][q] = 0.f;
    }
    float den = 0.f;

    for (int base = e0; base < e1; base += 32) {
        int cnt = min(32, e1 - base);
        if (lE < cnt) {
            int s = g_csr2[base + lE];
            if (hE == 0) sh_src[lE] = s;
            float a = g_es2[s * 4 + hE] + edv;
            a = a > 0.f ? a : 0.2f * a;
            float ex = __expf(a);
            sh_w[lE * 4 + hE] = ex;
            den += ex;
        }
        __syncthreads();
        if (cnt == 32) {
#pragma unroll 8
            for (int j = 0; j < 32; j++) {
                float4 v = *(const float4*)(g_h1 + (size_t)sh_src[j] * 512 + c);
                float4 w = *(const float4*)(sh_w + j * 4);
                acc[0][0] += w.x * v.x; acc[0][1] += w.x * v.y;
                acc[0][2] += w.x * v.z; acc[0][3] += w.x * v.w;
                acc[1][0] += w.y * v.x; acc[1][1] += w.y * v.y;
                acc[1][2] += w.y * v.z; acc[1][3] += w.y * v.w;
                acc[2][0] += w.z * v.x; acc[2][1] += w.z * v.y;
                acc[2][2] += w.z * v.z; acc[2][3] += w.z * v.w;
                acc[3][0] += w.w * v.x; acc[3][1] += w.w * v.y;
                acc[3][2] += w.w * v.z; acc[3][3] += w.w * v.w;
            }
        } else {
            for (int j = 0; j < cnt; j++) {
                float4 v = *(const float4*)(g_h1 + (size_t)sh_src[j] * 512 + c);
                float4 w = *(const float4*)(sh_w + j * 4);
                acc[0][0] += w.x * v.x; acc[0][1] += w.x * v.y;
                acc[0][2] += w.x * v.z; acc[0][3] += w.x * v.w;
                acc[1][0] += w.y * v.x; acc[1][1] += w.y * v.y;
                acc[1][2] += w.y * v.z; acc[1][3] += w.y * v.w;
                acc[2][0] += w.z * v.x; acc[2][1] += w.z * v.y;
                acc[2][2] += w.z * v.z; acc[2][3] += w.z * v.w;
                acc[3][0] += w.w * v.x; acc[3][1] += w.w * v.y;
                acc[3][2] += w.w * v.z; acc[3][3] += w.w * v.w;
            }
        }
        __syncthreads();
    }

    sh_red[t] = den;
    __syncthreads();
#pragma unroll
    for (int half = 16; half >= 1; half >>= 1) {
        if (lE < half) sh_red[t] += sh_red[t + half * 4];
        __syncthreads();
    }
    if (t < 4) {
        float a = g_es2[d * 4 + t] + sh_ed[t];
        a = a > 0.f ? a : 0.2f * a;
        float ex = __expf(a);
        sh_selfw[t] = ex;
        sh_den[t] = sh_red[t] + ex;
    }
    __syncthreads();

    float4 sv = *(const float4*)(g_h1 + (size_t)d * 512 + c);
    float svv[4];
    svv[0] = sv.x; svv[1] = sv.y; svv[2] = sv.z; svv[3] = sv.w;

    float contrib = 0.f;
#pragma unroll
    for (int h = 0; h < 4; h++) {
        float ws  = sh_selfw[h];
        float inv = 1.f / sh_den[h];
#pragma unroll
        for (int q = 0; q < 4; q++) {
            float a = (acc[h][q] + ws * svv[q]) * inv;
            contrib += a * g_w2v[h * 512 + c + q];
        }
    }
    contrib += flat[(size_t)d * 128 + t] * g_u[t];
    if (t < 64) contrib += last[(size_t)d * 64 + t] * oW[128 + t];

    sh_red[t] = contrib;
    __syncthreads();
#pragma unroll
    for (int half = 64; half >= 1; half >>= 1) {
        if (t < half) sh_red[t] += sh_red[t + half];
        __syncthreads();
    }
    if (t == 0) out[d] = sh_red[0] + g_c0;
}

// ---------------- tensor-core GEMM primitives ----------------
__device__ __forceinline__ void cp16(u32 sm, const void* gp) {
    asm volatile("cp.async.cg.shared.global [%0], [%1], 16;" : : "r"(sm), "l"(gp));
}
__device__ __forceinline__ void cp_commit() {
    asm volatile("cp.async.commit_group;" : :);
}
__device__ __forceinline__ void cp_wait1() {
    asm volatile("cp.async.wait_group 1;" : :);
}
__device__ __forceinline__ void cp_wait0() {
    asm volatile("cp.async.wait_group 0;" : :);
}
__device__ __forceinline__ void ldsm4(u32* r, u32 a) {
    asm volatile("ldmatrix.sync.aligned.m8n8.x4.shared.b16 {%0,%1,%2,%3}, [%4];"
                 : "=r"(r[0]), "=r"(r[1]), "=r"(r[2]), "=r"(r[3]) : "r"(a));
}
__device__ __forceinline__ void ldsm2(u32* r, u32 a) {
    asm volatile("ldmatrix.sync.aligned.m8n8.x2.shared.b16 {%0,%1}, [%2];"
                 : "=r"(r[0]), "=r"(r[1]) : "r"(a));
}
__device__ __forceinline__ void mma16816(float* d, const u32* a, const u32* b) {
    asm volatile("mma.sync.aligned.m16n8k16.row.col.f32.bf16.bf16.f32 "
                 "{%0,%1,%2,%3}, {%4,%5,%6,%7}, {%8,%9}, {%0,%1,%2,%3};"
                 : "+f"(d[0]), "+f"(d[1]), "+f"(d[2]), "+f"(d[3])
                 : "r"(a[0]), "r"(a[1]), "r"(a[2]), "r"(a[3]), "r"(b[0]), "r"(b[1]));
}

// stage loader: A tile 128x32 (row stride 4096), two B tiles 64x32 (row stride 512)
__device__ __forceinline__ void gload(const __nv_bfloat16* A, const __nv_bfloat16* B,
                                      u32 sA, u32 sB0, u32 sB1, int tid, int bm,
                                      int ak0, int b0k, int b1k) {
#pragma unroll
    for (int i = 0; i < 2; i++) {
        int cc = tid + i * 256;
        int row = cc >> 2;
        int kc = (cc & 3) << 3;
        cp16(sA + row * 80 + kc * 2, (const void*)(A + (size_t)(bm + row) * 4096 + ak0 + kc));
    }
    {
        int row = tid >> 2;
        int kc = (tid & 3) << 3;
        cp16(sB0 + row * 80 + kc * 2, (const void*)(B + (size_t)row * 512 + b0k + kc));
        cp16(sB1 + row * 80 + kc * 2, (const void*)(B + (size_t)row * 512 + b1k + kc));
    }
}

// conv1 GEMM: per-head, D = Ah*Bh + Ah*Bl + Al*Bh with A-hi loaded ONCE.
// 16 macro iters: it 0..7 (A-hi x {Bh,Bl}), it 8..15 (A-lo x Bh).
// 128x64 CTA tile, 8 warps (4m x 2n), double-buffered. grid (125, 8).
__global__ void __launch_bounds__(256) k_mma(const float* __restrict__ bias) {
    int head = blockIdx.y;
    const __nv_bfloat16* A = g_x1a + (size_t)head * 512;
    const __nv_bfloat16* B = g_w1a + (size_t)head * 64 * 512;

    __shared__ __nv_bfloat16 smem[20480];   // 40960 B = 2 stages x (10240+5120+5120)
    const int tid  = threadIdx.x;
    const int lane = tid & 31;
    const int w    = tid >> 5;
    const int wm   = (w >> 1) * 32;
    const int wn   = (w & 1) * 32;
    const int bm   = blockIdx.x * 128;
    const u32 sbase = (u32)__cvta_generic_to_shared(smem);

    float acc[2][4][4];
#pragma unroll
    for (int i = 0; i < 2; i++) {
#pragma unroll
        for (int j = 0; j < 4; j++) {
#pragma unroll
            for (int q = 0; q < 4; q++) acc[i][j][q] = 0.f;
        }
    }

    gload(A, B, sbase, sbase + 10240, sbase + 15360, tid, bm, 0, 0, 256);
    cp_commit();

    for (int it = 0; it < 16; it++) {
        if (it + 1 < 16) {
            int ni = it + 1;
            int ak0 = (ni < 8) ? ni * 32 : 256 + (ni - 8) * 32;
            int b0k = (ni < 8) ? ni * 32 : (ni - 8) * 32;
            int b1k = (ni < 8) ? 256 + ni * 32 : (ni - 8) * 32;
            u32 s = (ni & 1) ? (sbase + 20480) : sbase;
            gload(A, B, s, s + 10240, s + 15360, tid, bm, ak0, b0k, b1k);
            cp_commit();
            cp_wait1();
        } else {
            cp_wait0();
        }
        __syncthreads();
        u32 sA  = (it & 1) ? (sbase + 20480) : sbase;
        u32 sB0 = sA + 10240;
        u32 sB1 = sA + 15360;
#pragma unroll
        for (int kk = 0; kk < 2; kk++) {
            u32 a[2][4];
            u32 b[4][2];
#pragma unroll
            for (int i = 0; i < 2; i++) {
                int row = wm + i * 16 + (lane & 15);
                int ko  = kk * 16 + (lane >> 4) * 8;
                ldsm4(a[i], sA + row * 80 + ko * 2);
            }
#pragma unroll
            for (int j = 0; j < 4; j++) {
                int row = wn + j * 8 + (lane & 7);
                int ko  = kk * 16 + ((lane >> 3) & 1) * 8;
                ldsm2(b[j], sB0 + row * 80 + ko * 2);
            }
#pragma unroll
            for (int i = 0; i < 2; i++) {
#pragma unroll
                for (int j = 0; j < 4; j++) mma16816(acc[i][j], a[i], b[j]);
            }
            if (it < 8) {
#pragma unroll
                for (int j = 0; j < 4; j++) {
                    int row = wn + j * 8 + (lane & 7);
                    int ko  = kk * 16 + ((lane >> 3) & 1) * 8;
                    ldsm2(b[j], sB1 + row * 80 + ko * 2);
                }
#pragma unroll
                for (int i = 0; i < 2; i++) {
#pragma unroll
                    for (int j = 0; j < 4; j++) mma16816(acc[i][j], a[i], b[j]);
                }
            }
        }
        __syncthreads();
    }

#pragma unroll
    for (int i = 0; i < 2; i++) {
        int row = bm + wm + i * 16 + (lane >> 2);
#pragma unroll
        for (int j = 0; j < 4; j++) {
            int col = wn + j * 8 + (lane & 3) * 2;
            int gc = head * 64 + col;
            float b0 = bias[gc], b1v = bias[gc + 1];
            float o0 = acc[i][j][0] + b0;
            float o1 = acc[i][j][1] + b1v;
            float o2 = acc[i][j][2] + b0;
            float o3 = acc[i][j][3] + b1v;
            o0 = o0 > 0.f ? o0 : expm1f(o0);
            o1 = o1 > 0.f ? o1 : expm1f(o1);
            o2 = o2 > 0.f ? o2 : expm1f(o2);
            o3 = o3 > 0.f ? o3 : expm1f(o3);
            float2 v0; v0.x = o0; v0.y = o1;
            float2 v1; v1.x = o2; v1.y = o3;
            *(float2*)(g_h1 + (size_t)row * 512 + gc)       = v0;
            *(float2*)(g_h1 + (size_t)(row + 8) * 512 + gc) = v1;
        }
    }
}

// ---------------- launch ----------------
extern "C" void kernel_launch(void* const* d_in, const int* in_sizes, int n_in,
                              void* d_out, int out_size) {
    const float* x    = (const float*)d_in[0];
    const float* flat = (const float*)d_in[1];
    const float* last = (const float*)d_in[2];
    const int* esrc1  = (const int*)d_in[3];
    const int* edst1  = (const int*)d_in[4];
    const int* esrc2  = (const int*)d_in[5];
    const int* edst2  = (const int*)d_in[6];
    const float* W1s  = (const float*)d_in[7];
    const float* W1d  = (const float*)d_in[8];
    const float* a1s  = (const float*)d_in[9];
    const float* a1d  = (const float*)d_in[10];
    const float* b1   = (const float*)d_in[11];
    const float* W2s  = (const float*)d_in[12];
    const float* W2d  = (const float*)d_in[13];
    const float* a2s  = (const float*)d_in[14];
    const float* a2d  = (const float*)d_in[15];
    const float* b2   = (const float*)d_in[16];
    const float* fW   = (const float*)d_in[17];
    const float* fb   = (const float*)d_in[18];
    const float* oW   = (const float*)d_in[19];
    const float* ob   = (const float*)d_in[20];
    float* out        = (float*)d_out;

    (void)in_sizes;
    (void)n_in;
    (void)out_size;

    k_setup<<<1809, 256>>>(W1s, W1d, a1s, a1d, W2s, W2d, a2s, a2d,
                           fW, fb, oW, ob, b2, edst1, edst2);
    k_scan<<<2, 1024>>>();
    k_scsc<<<1256 + 10000, 256>>>(esrc1, edst1, esrc2, edst2, x);

    k_agg1x<<<kN2, 128>>>(x);
    k_mma<<<dim3(125, 8), 256>>>(b1);

    k_scores2<<<(kN2 * 32) / 256, 256>>>();
    k_agg2x<<<kN3, 128>>>(flat, last, oW, out);
}